// round 15
// baseline (speedup 1.0000x reference)
#include <cuda_runtime.h>
#include <cuda_fp16.h>
#include <math.h>

#define NB 16
#define NA 720
#define ND 1024
#define NH 512
#define NW 512
#define PI_F 3.14159265358979323846f

// Filtered sinogram in fp16: g_v[g2][a][bin] = uint4 record of 8 batches
// (batches 8*g2 .. 8*g2+7, stored as 4 half2). 23.6 MB, L2-resident.
__device__ uint4 g_v[2 * NA * ND];

__device__ __forceinline__ float2 cmulf(float2 a, float2 b) {
    return make_float2(a.x * b.x - a.y * b.y, a.x * b.y + a.y * b.x);
}
__device__ __forceinline__ unsigned int h2_as_u32(__half2 h) {
    return *reinterpret_cast<unsigned int*>(&h);
}
__device__ __forceinline__ __half2 u32_as_h2(unsigned int u) {
    return *reinterpret_cast<__half2*>(&u);
}

// -------------------------------------------------------------------------
// Kernel 1: ramp filter via complex-pair Stockham FFT (filter real & even:
// FFT(u+iv)*f -> re=filt(u), im=filt(v) exactly). Block = (angle a, batch
// pair m). Stores fp16 v into planar array (u32 slot p = m&3).
// -------------------------------------------------------------------------
__global__ __launch_bounds__(512) void fbp_filter_kernel(
    const float* __restrict__ sino, const float* __restrict__ filt)
{
    __shared__ float2 bufA[ND];
    __shared__ float2 bufB[ND];
    __shared__ float2 tw[ND / 2];

    const int a = blockIdx.x;
    const int m = blockIdx.y;       // batches 2m, 2m+1
    const int tid = threadIdx.x;

    const float* u = sino + ((size_t)(2 * m) * NA + a) * ND;
    const float* v = sino + ((size_t)(2 * m + 1) * NA + a) * ND;

    bufA[tid]       = make_float2(u[tid],       v[tid]);
    bufA[tid + 512] = make_float2(u[tid + 512], v[tid + 512]);
    {
        float sv, cv;
        sincosf((-2.0f * PI_F / ND) * (float)tid, &sv, &cv);
        tw[tid] = make_float2(cv, sv);
    }
    __syncthreads();

    float2* x = bufA;
    float2* y = bufB;

    #pragma unroll
    for (int stage = 0; stage < 10; ++stage) {
        const int s  = 1 << stage;
        const int q  = tid & (s - 1);
        const int ps = tid - q;
        float2 aa = x[tid];
        float2 bb = x[tid + 512];
        float2 w = tw[ps];
        y[2 * ps + q]     = make_float2(aa.x + bb.x, aa.y + bb.y);
        y[2 * ps + s + q] = cmulf(make_float2(aa.x - bb.x, aa.y - bb.y), w);
        __syncthreads();
        float2* t = x; x = y; y = t;
    }
    {
        float f0 = filt[tid], f1 = filt[tid + 512];
        float2 aa = x[tid];       aa.x *= f0; aa.y *= f0; x[tid]       = aa;
        float2 bb = x[tid + 512]; bb.x *= f1; bb.y *= f1; x[tid + 512] = bb;
    }
    __syncthreads();
    #pragma unroll
    for (int stage = 0; stage < 10; ++stage) {
        const int s  = 1 << stage;
        const int q  = tid & (s - 1);
        const int ps = tid - q;
        float2 aa = x[tid];
        float2 bb = x[tid + 512];
        float2 w = tw[ps]; w.y = -w.y;
        y[2 * ps + q]     = make_float2(aa.x + bb.x, aa.y + bb.y);
        y[2 * ps + s + q] = cmulf(make_float2(aa.x - bb.x, aa.y - bb.y), w);
        __syncthreads();
        float2* t = x; x = y; y = t;
    }

    const float invN = 1.0f / (float)ND;
    const int g2 = m >> 2;
    const int p  = m & 3;
    unsigned int* ov = (unsigned int*)g_v;
    const size_t base_u = ((size_t)(g2 * NA + a) * ND) * 4;

    {   // bin = tid
        float2 c = x[tid];
        ov[base_u + (size_t)tid * 4 + p] =
            h2_as_u32(__floats2half2_rn(c.x * invN, c.y * invN));
    }
    {   // bin = tid + 512
        float2 c = x[tid + 512];
        ov[base_u + (size_t)(tid + 512) * 4 + p] =
            h2_as_u32(__floats2half2_rn(c.x * invN, c.y * invN));
    }
}

// -------------------------------------------------------------------------
// Kernel 2: backprojection. Warp-cooperative 16-bin v-windows, 2 angles per
// LDG (lanes 0-15: angle 2p, 16-31: angle 2p+1), magic-number floor,
// lerp = 2 HFMA2/word, ww = 1 - w via HSUB2.
// DEPTH-3 LDG pipeline, 48-reg cap (launch_bounds 256x5 -> 40 resident
// warps x 3 outstanding = 120 LDGs in flight; R14's 64 regs capped us at
// ~29 warps -> 86% L1). Slot state slimmed to {r, packed(bm0,bm1)}:
// magic-float low-16 bits == bin (bins < 1024, base低16 = 0), so the
// shuffle index from 16-bit masked subtraction is borrow-free and
// bit-identical to the full-word subtraction.
//
// Magic floor: fr = (t-0.5)+(2^23+2^22) rounds to i0' in {floor(t)-1,
// floor(t)}; w = t-i0' in [0,1] exact; window corner uses the same
// arithmetic, -1 margin -> idx in [0,11] <= 15, idx+1 <= 12; window
// [148,886] subset of [0,1023].
// -------------------------------------------------------------------------
__global__ __launch_bounds__(256, 5) void fbp_backproj_kernel(float* __restrict__ out)
{
    __shared__ float4 cs2[NA / 2];   // (c0,s0,c1,s1) per angle pair

    const int tid = threadIdx.x;
    for (int i = tid; i < NA / 2; i += 256) {
        float s0, c0, s1, c1;
        sincosf((PI_F / (float)NA) * (float)(2 * i),     &s0, &c0);
        sincosf((PI_F / (float)NA) * (float)(2 * i + 1), &s1, &c1);
        cs2[i] = make_float4(c0, s0, c1, s1);
    }
    __syncthreads();

    const float MAGIC = 12582912.0f;                     // 2^23 + 2^22
    const float Cm    = 0.5f * (float)(ND - 1) - 0.5f;   // C - 0.5

    const int wrp  = tid >> 5;
    const int lane = tid & 31;
    const int xb = (blockIdx.x << 4) + ((wrp & 1) << 3);
    const int yb = (blockIdx.y << 4) + ((wrp >> 1) << 2);
    const int x = xb + (lane & 7);
    const int y = yb + (lane >> 3);
    const float px  = (float)x - 0.5f * (float)(NW - 1);
    const float py  = (float)y - 0.5f * (float)(NH - 1);
    const float pxb = (float)xb - 0.5f * (float)(NW - 1);
    const float pyb = (float)yb - 0.5f * (float)(NH - 1);

    const int g2 = blockIdx.z;
    const uint4* __restrict__ vb = g_v + (size_t)g2 * NA * ND;
    const int lanehalf = lane >> 4;
    const int lanelow  = lane & 15;
    const __half2 ONE2 = __float2half2_rn(1.0f);

    float acc[8];
    #pragma unroll
    for (int j = 0; j < 8; ++j) acc[j] = 0.0f;

    // ---- depth-3 pipeline state (slim: r + packed corner bins) ----
    unsigned int bmp[3];     // low16: bin0, high16: bin1
    uint4 rs[3];

#define PREFETCH(IDX, SLOT) do {                                               \
        int _p = (IDX); if (_p >= NA / 2) _p -= NA / 2;                        \
        float4 _q = cs2[_p];                                                   \
        float _pxm0 = (_q.x < 0.0f) ? pxb + 7.0f : pxb;                        \
        float _pxm1 = (_q.z < 0.0f) ? pxb + 7.0f : pxb;                        \
        unsigned _b0 = __float_as_uint(__fadd_rn(fmaf(_pxm0, _q.x,             \
                        fmaf(pyb, _q.y, Cm)), MAGIC)) & 0xFFFFu;               \
        unsigned _b1 = __float_as_uint(__fadd_rn(fmaf(_pxm1, _q.z,             \
                        fmaf(pyb, _q.w, Cm)), MAGIC)) & 0xFFFFu;               \
        int _ib = (int)(lanehalf ? _b1 : _b0) - 1;                             \
        rs[SLOT]  = vb[(2 * _p + lanehalf) * ND + _ib + lanelow];              \
        bmp[SLOT] = _b0 | (_b1 << 16);                                         \
    } while (0)

    PREFETCH(0, 0);
    PREFETCH(1, 1);
    PREFETCH(2, 2);

    for (int p = 0; p < NA / 2; p += 12) {       // 30 outer iterations
        __half2 h0 = __float2half2_rn(0.0f);
        __half2 h1 = h0, h2 = h0, h3 = h0;

        #pragma unroll
        for (int j = 0; j < 12; ++j) {
            const int slot = j % 3;              // compile-time (j literal)
            float4 q = cs2[p + j];               // LDS.128 broadcast
            unsigned bm = bmp[slot];
            uint4 r = rs[slot];
            PREFETCH(p + j + 3, slot);

            // angle 2(p+j) (window lanes 0-15)
            {
                float ft = fmaf(px, q.x, fmaf(py, q.y, Cm));
                float fr = __fadd_rn(ft, MAGIC);
                float fi = __fsub_rn(fr, MAGIC);
                float d  = __fsub_rn(ft, fi);            // [-0.5, 0.5] exact
                __half2 w2  = __float2half2_rn(__fadd_rn(d, 0.5f));
                __half2 ww2 = __hsub2(ONE2, w2);
                int s0i = (int)(__float_as_uint(fr) & 0xFFFFu)
                        - (int)(bm & 0xFFFFu) + 1;       // [0,11]
                int s1i = s0i + 1;

                __half2 vx = u32_as_h2(__shfl_sync(0xffffffffu, r.x, s0i));
                __half2 vy = u32_as_h2(__shfl_sync(0xffffffffu, r.y, s0i));
                __half2 vz = u32_as_h2(__shfl_sync(0xffffffffu, r.z, s0i));
                __half2 vw = u32_as_h2(__shfl_sync(0xffffffffu, r.w, s0i));
                __half2 ux = u32_as_h2(__shfl_sync(0xffffffffu, r.x, s1i));
                __half2 uy = u32_as_h2(__shfl_sync(0xffffffffu, r.y, s1i));
                __half2 uz = u32_as_h2(__shfl_sync(0xffffffffu, r.z, s1i));
                __half2 uw = u32_as_h2(__shfl_sync(0xffffffffu, r.w, s1i));

                h0 = __hfma2(ww2, vx, __hfma2(w2, ux, h0));
                h1 = __hfma2(ww2, vy, __hfma2(w2, uy, h1));
                h2 = __hfma2(ww2, vz, __hfma2(w2, uz, h2));
                h3 = __hfma2(ww2, vw, __hfma2(w2, uw, h3));
            }
            // angle 2(p+j)+1 (window lanes 16-31)
            {
                float ft = fmaf(px, q.z, fmaf(py, q.w, Cm));
                float fr = __fadd_rn(ft, MAGIC);
                float fi = __fsub_rn(fr, MAGIC);
                float d  = __fsub_rn(ft, fi);
                __half2 w2  = __float2half2_rn(__fadd_rn(d, 0.5f));
                __half2 ww2 = __hsub2(ONE2, w2);
                int s0i = (int)(__float_as_uint(fr) & 0xFFFFu)
                        - (int)(bm >> 16) + 17;          // [16,27]
                int s1i = s0i + 1;

                __half2 vx = u32_as_h2(__shfl_sync(0xffffffffu, r.x, s0i));
                __half2 vy = u32_as_h2(__shfl_sync(0xffffffffu, r.y, s0i));
                __half2 vz = u32_as_h2(__shfl_sync(0xffffffffu, r.z, s0i));
                __half2 vw = u32_as_h2(__shfl_sync(0xffffffffu, r.w, s0i));
                __half2 ux = u32_as_h2(__shfl_sync(0xffffffffu, r.x, s1i));
                __half2 uy = u32_as_h2(__shfl_sync(0xffffffffu, r.y, s1i));
                __half2 uz = u32_as_h2(__shfl_sync(0xffffffffu, r.z, s1i));
                __half2 uw = u32_as_h2(__shfl_sync(0xffffffffu, r.w, s1i));

                h0 = __hfma2(ww2, vx, __hfma2(w2, ux, h0));
                h1 = __hfma2(ww2, vy, __hfma2(w2, uy, h1));
                h2 = __hfma2(ww2, vz, __hfma2(w2, uz, h2));
                h3 = __hfma2(ww2, vw, __hfma2(w2, uw, h3));
            }

            if ((j & 3) == 3) {                  // flush every 4 pairs = 8 angles
                acc[0] += __low2float(h0);  acc[1] += __high2float(h0);
                acc[2] += __low2float(h1);  acc[3] += __high2float(h1);
                acc[4] += __low2float(h2);  acc[5] += __high2float(h2);
                acc[6] += __low2float(h3);  acc[7] += __high2float(h3);
                h0 = __float2half2_rn(0.0f);
                h1 = h0; h2 = h0; h3 = h0;
            }
        }
    }
#undef PREFETCH

    const float scale = PI_F / (float)NA;
    const size_t pix = (size_t)y * NW + x;
    const size_t HW = (size_t)NH * NW;
    float* dst = out + (size_t)(8 * g2) * HW + pix;
    #pragma unroll
    for (int j = 0; j < 8; ++j)
        dst[(size_t)j * HW] = acc[j] * scale;
}

extern "C" void kernel_launch(void* const* d_in, const int* in_sizes, int n_in,
                              void* d_out, int out_size)
{
    const float* sino = (const float*)d_in[0];   // (16, 720, 1024) fp32
    const float* filt = (const float*)d_in[1];   // (1024,) fp32
    float* out = (float*)d_out;                  // (16, 512, 512) fp32

    dim3 fgrid(NA, NB / 2);
    fbp_filter_kernel<<<fgrid, 512>>>(sino, filt);

    dim3 bgrid(NW / 16, NH / 16, 2);
    fbp_backproj_kernel<<<bgrid, 256>>>(out);
}